// round 11
// baseline (speedup 1.0000x reference)
#include <cuda_runtime.h>

// NeuralODEClassifier, two kernels.
// K1 (ODE): quad = 4 lanes/element, 16 hidden units/lane, 2 elements/thread
//   (R9 org — proven best parallelism point). NEW: packed f32x2 accumulation
//   (accP/accQ per element, natural {r0,r1}/{r2,r3} pairs vs V-pairs from
//   shared) cuts FMA-pipe ops/group 25->21. occ 7 (73-reg cap) keeps the
//   1024-CTA grid in a single wave with headroom for the packed accs.
// K2 (classifier): NEW 2 threads/element: each lane owns 32 h1 units in
//   registers, accumulates partial h2 sums over its k-half for all 64 j in
//   chunks of 8, shfl-combines with its partner, lane 0 applies ReLU+Wc3.
//   4096 warps (2x previous), single wave.
//
// tanh(z) = 1 - 2/(2^(C*z)+1), C = 2*log2(e); W1/b1 prescaled by C, the
// (1-2r) fold absorbed into W2 (v = -2*W2, S = colsum(W2)+b2).

#define H 64
#define TT 64
#define NCLS 3
#define BMAX 65536

typedef unsigned long long u64;

__device__ float g_yT[BMAX * 2];

__device__ __forceinline__ float fast_ex2(float x) {
    float r; asm("ex2.approx.f32 %0, %1;" : "=f"(r) : "f"(x)); return r;
}
__device__ __forceinline__ float fast_rcp(float x) {
    float r; asm("rcp.approx.f32 %0, %1;" : "=f"(r) : "f"(x)); return r;
}
__device__ __forceinline__ u64 pk2(float lo, float hi) {
    u64 r; asm("mov.b64 %0, {%1, %2};" : "=l"(r) : "f"(lo), "f"(hi)); return r;
}
__device__ __forceinline__ void unpk2(u64 v, float& lo, float& hi) {
    asm("mov.b64 {%0, %1}, %2;" : "=f"(lo), "=f"(hi) : "l"(v));
}
__device__ __forceinline__ u64 fma2(u64 a, u64 b, u64 c) {
    u64 d; asm("fma.rn.f32x2 %0, %1, %2, %3;" : "=l"(d) : "l"(a), "l"(b), "l"(c));
    return d;
}

// unit u = q*16 + g*4 + c  ->  float slot ((g*4+q)*4 + c).
// For fixed g the 4 quad-lanes read 4 consecutive 16B chunks: conflict-free.
#define PK(g, q, c) (((g) * 4 + (q)) * 4 + (c))

// ---------------------------------------------------------------- K1: ODE ---
__global__ __launch_bounds__(128, 7)
void node_ode_kernel(
    const float* __restrict__ y0g,  const float* __restrict__ tg,
    const float* __restrict__ W1,   const float* __restrict__ b1,
    const float* __restrict__ W2,   const float* __restrict__ b2,
    int B)
{
    __shared__ __align__(16) float sWA[H];   // W1 row0 * C, packed
    __shared__ __align__(16) float sWB[H];   // W1 row1 * C, packed
    __shared__ __align__(16) float sBB[H];   // b1  * C, packed
    __shared__ __align__(16) float sV0[H];   // -2*W2[u][0], packed
    __shared__ __align__(16) float sV1[H];   // -2*W2[u][1], packed
    __shared__ float sS[2];
    __shared__ float sdt[TT - 1];

    const float C = 2.88539008177792681472f; // 2*log2(e)
    const int tid = threadIdx.x;

    if (tid < H) {
        int u = tid;
        int q = u >> 4, rr = u & 15, g = rr >> 2, c = rr & 3;
        int p = PK(g, q, c);
        sWA[p] = W1[u] * C;
        sWB[p] = W1[H + u] * C;
        sBB[p] = b1[u] * C;
        sV0[p] = -2.0f * W2[u * 2 + 0];
        sV1[p] = -2.0f * W2[u * 2 + 1];
    }
    if (tid >= H && tid < H + 2) {
        int c = tid - H;
        float s = b2[c];
        #pragma unroll 8
        for (int j = 0; j < H; j++) s += W2[j * 2 + c];
        sS[c] = s;
    }
    for (int i = tid; i < TT - 1; i += 128)
        sdt[i] = tg[i + 1] - tg[i];
    __syncthreads();

    const int gid = blockIdx.x * 128 + tid;
    const int eA = gid >> 2;           // first element
    const int q  = gid & 3;            // quad slot
    const int half = B >> 1;
    if (eA >= half) return;
    const int eB = eA + half;          // second element

    float ya[2], yb[2];
    ya[0] = y0g[eA * 2 + 0]; yb[0] = y0g[eA * 2 + 1];
    ya[1] = y0g[eB * 2 + 0]; yb[1] = y0g[eB * 2 + 1];
    const float S0 = sS[0], S1 = sS[1];

    for (int s = 0; s < TT - 1; s++) {
        const float dt = sdt[s];
        u64 pa[2], pb[2], accP[2], accQ[2];
        #pragma unroll
        for (int m = 0; m < 2; m++) {
            pa[m] = pk2(ya[m], ya[m]);
            pb[m] = pk2(yb[m], yb[m]);
            accP[m] = 0; accQ[m] = 0;
        }

        #pragma unroll
        for (int g = 0; g < 4; g++) {
            const int base = PK(g, q, 0);
            const ulonglong2 WA = *(const ulonglong2*)&sWA[base];
            const ulonglong2 WB = *(const ulonglong2*)&sWB[base];
            const ulonglong2 BB = *(const ulonglong2*)&sBB[base];
            const ulonglong2 V0p = *(const ulonglong2*)&sV0[base]; // {v0_u0,v0_u1},{v0_u2,v0_u3}
            const ulonglong2 V1p = *(const ulonglong2*)&sV1[base];

            #pragma unroll
            for (int m = 0; m < 2; m++) {
                u64 w01 = fma2(pa[m], WA.x, fma2(pb[m], WB.x, BB.x));
                u64 w23 = fma2(pa[m], WA.y, fma2(pb[m], WB.y, BB.y));
                float w0, w1, w2, w3;
                unpk2(w01, w0, w1);
                unpk2(w23, w2, w3);
                w0 = fminf(w0, 30.0f); w1 = fminf(w1, 30.0f);
                w2 = fminf(w2, 30.0f); w3 = fminf(w3, 30.0f);

                float a0 = fast_ex2(w0) + 1.0f;
                float a1 = fast_ex2(w1) + 1.0f;
                float a2 = fast_ex2(w2) + 1.0f;
                float a3 = fast_ex2(w3) + 1.0f;

                float p01 = a0 * a1, p23 = a2 * a3;
                float rinv = fast_rcp(p01 * p23);
                float q01 = rinv * p23, q23 = rinv * p01;
                float r0 = q01 * a1, r1 = q01 * a0;
                float r2 = q23 * a3, r3 = q23 * a2;

                const u64 r01 = pk2(r0, r1);
                const u64 r23 = pk2(r2, r3);
                accP[m] = fma2(r01, V0p.x, accP[m]);
                accP[m] = fma2(r23, V0p.y, accP[m]);
                accQ[m] = fma2(r01, V1p.x, accQ[m]);
                accQ[m] = fma2(r23, V1p.y, accQ[m]);
            }
        }

        #pragma unroll
        for (int m = 0; m < 2; m++) {
            float pl, ph, ql, qh;
            unpk2(accP[m], pl, ph);
            unpk2(accQ[m], ql, qh);
            float acc0 = pl + ph;
            float acc1 = ql + qh;
            acc0 += __shfl_xor_sync(0xffffffffu, acc0, 1);
            acc0 += __shfl_xor_sync(0xffffffffu, acc0, 2);
            acc1 += __shfl_xor_sync(0xffffffffu, acc1, 1);
            acc1 += __shfl_xor_sync(0xffffffffu, acc1, 2);
            ya[m] = fmaf(dt, S0 + acc0, ya[m]);   // identical across quad
            yb[m] = fmaf(dt, S1 + acc1, yb[m]);
        }
    }

    if (q == 0) {
        g_yT[eA * 2 + 0] = ya[0]; g_yT[eA * 2 + 1] = yb[0];
        g_yT[eB * 2 + 0] = ya[1]; g_yT[eB * 2 + 1] = yb[1];
    }
}

// --------------------------------------------------------- K2: classifier ---
// 2 threads per element: lane p owns h1 units [p*32, p*32+32) in registers.
// For each chunk of 8 output units j, both lanes accumulate partial sums over
// their own 32 k's, shfl_xor(1)-combine, lane 0 applies ReLU + Wc3.
__global__ __launch_bounds__(128, 8)
void node_cls_kernel(
    const float* __restrict__ Wc1,  const float* __restrict__ bc1,
    const float* __restrict__ Wc2,  const float* __restrict__ bc2,
    const float* __restrict__ Wc3,  const float* __restrict__ bc3,
    float* __restrict__ out, int B)
{
    __shared__ __align__(16) float sWc1A[H], sWc1B[H], sbc1[H];
    __shared__ __align__(16) float sWc2T[H][H];  // [out_j][in_k]
    __shared__ __align__(16) float sbc2[H];
    __shared__ __align__(16) float4 sWc3[H];     // {w0,w1,w2,0}
    __shared__ float sbc3[NCLS];

    const int tid = threadIdx.x;
    if (tid < H) {
        sWc1A[tid] = Wc1[tid];
        sWc1B[tid] = Wc1[H + tid];
        sbc1[tid]  = bc1[tid];
        sbc2[tid]  = bc2[tid];
        sWc3[tid]  = make_float4(Wc3[tid * 3 + 0], Wc3[tid * 3 + 1],
                                 Wc3[tid * 3 + 2], 0.0f);
    }
    if (tid < NCLS) sbc3[tid] = bc3[tid];
    for (int i = tid; i < H * H; i += 128) {
        sWc2T[i & 63][i >> 6] = Wc2[i];
    }
    __syncthreads();

    const int gid = blockIdx.x * 128 + tid;
    const int e = gid >> 1;            // element
    const int p = gid & 1;             // pair slot
    if (e >= B) return;

    const float ya = g_yT[e * 2 + 0];
    const float yb = g_yT[e * 2 + 1];

    // my 32 h1 units: k in [p*32, p*32+32)
    const int k0 = p * 32;
    float h1[32];
    #pragma unroll
    for (int i = 0; i < 32; i += 4) {
        const float4 wa = *(const float4*)&sWc1A[k0 + i];
        const float4 wb = *(const float4*)&sWc1B[k0 + i];
        const float4 bb = *(const float4*)&sbc1[k0 + i];
        h1[i + 0] = fmaxf(fmaf(ya, wa.x, fmaf(yb, wb.x, bb.x)), 0.0f);
        h1[i + 1] = fmaxf(fmaf(ya, wa.y, fmaf(yb, wb.y, bb.y)), 0.0f);
        h1[i + 2] = fmaxf(fmaf(ya, wa.z, fmaf(yb, wb.z, bb.z)), 0.0f);
        h1[i + 3] = fmaxf(fmaf(ya, wa.w, fmaf(yb, wb.w, bb.w)), 0.0f);
    }

    float o0 = 0.f, o1 = 0.f, o2 = 0.f;
    #pragma unroll
    for (int jc = 0; jc < 8; jc++) {
        const int j0 = jc * 8;
        float acc[8];
        #pragma unroll
        for (int jj = 0; jj < 8; jj++)
            acc[jj] = (p == 0) ? sbc2[j0 + jj] : 0.0f;   // bias counted once

        #pragma unroll
        for (int jj = 0; jj < 8; jj++) {
            const float* row = &sWc2T[j0 + jj][k0];
            float s0 = acc[jj], s1 = 0.f;
            #pragma unroll
            for (int i = 0; i < 32; i += 8) {
                const float4 wA = *(const float4*)&row[i];
                const float4 wB = *(const float4*)&row[i + 4];
                s0 = fmaf(h1[i + 0], wA.x, s0);
                s1 = fmaf(h1[i + 1], wA.y, s1);
                s0 = fmaf(h1[i + 2], wA.z, s0);
                s1 = fmaf(h1[i + 3], wA.w, s1);
                s0 = fmaf(h1[i + 4], wB.x, s0);
                s1 = fmaf(h1[i + 5], wB.y, s1);
                s0 = fmaf(h1[i + 6], wB.z, s0);
                s1 = fmaf(h1[i + 7], wB.w, s1);
            }
            acc[jj] = s0 + s1;
        }

        #pragma unroll
        for (int jj = 0; jj < 8; jj++) {
            acc[jj] += __shfl_xor_sync(0xffffffffu, acc[jj], 1);
            if (p == 0) {
                const float hv = fmaxf(acc[jj], 0.0f);
                const float4 wc = sWc3[j0 + jj];
                o0 = fmaf(hv, wc.x, o0);
                o1 = fmaf(hv, wc.y, o1);
                o2 = fmaf(hv, wc.z, o2);
            }
        }
    }

    if (p == 0) {
        out[e * 3 + 0] = o0 + sbc3[0];
        out[e * 3 + 1] = o1 + sbc3[1];
        out[e * 3 + 2] = o2 + sbc3[2];
    }
}

extern "C" void kernel_launch(void* const* d_in, const int* in_sizes, int n_in,
                              void* d_out, int out_size) {
    const float* y0  = (const float*)d_in[0];
    const float* t   = (const float*)d_in[1];
    const float* W1  = (const float*)d_in[2];
    const float* b1  = (const float*)d_in[3];
    const float* W2  = (const float*)d_in[4];
    const float* b2  = (const float*)d_in[5];
    const float* Wc1 = (const float*)d_in[6];
    const float* bc1 = (const float*)d_in[7];
    const float* Wc2 = (const float*)d_in[8];
    const float* bc2 = (const float*)d_in[9];
    const float* Wc3 = (const float*)d_in[10];
    const float* bc3 = (const float*)d_in[11];
    float* out = (float*)d_out;

    const int B = in_sizes[0] / 2;
    const long long thOde = (long long)B * 2;   // 4 lanes/elem, 2 elems/thread
    const long long thCls = (long long)B * 2;   // 2 lanes/elem
    node_ode_kernel<<<(int)((thOde + 127) / 128), 128>>>(y0, t, W1, b1, W2, b2, B);
    node_cls_kernel<<<(int)((thCls + 127) / 128), 128>>>(Wc1, bc1, Wc2, bc2,
                                                         Wc3, bc3, out, B);
}

// round 12
// speedup vs baseline: 2.0887x; 2.0887x over previous
#include <cuda_runtime.h>

// NeuralODEClassifier, two kernels (R9 baseline + two micro-opts).
// K1 (ODE): quad = 4 lanes/element, 16 hidden units/lane, 2 elements/thread.
//   Weights in shared (conflict-free quad packing). Batched-rcp sigmoid with
//   fma-fold: a1/a3 never materialized (p01=fma(a0,E1,a0), r0=fma(q01,E1,q01))
//   -> 23 fma-pipe ops/group (was 25). f32x2 packed FMA for the input MLP.
//   64-reg budget (occ 8), 1024 CTAs single wave.
// K2 (classifier): 1 thread/elem (perfect warp-broadcast LDS), block 64 so the
//   1024-CTA grid balances across 148 SMs (was 512 CTAs -> 16% tail).
//
// tanh(z) = 1 - 2/(2^(C*z)+1), C = 2*log2(e); W1/b1 prescaled by C, the
// (1-2r) fold absorbed into W2 (v = -2*W2, S = colsum(W2)+b2).

#define H 64
#define TT 64
#define NCLS 3
#define BMAX 65536

typedef unsigned long long u64;

__device__ float g_yT[BMAX * 2];

__device__ __forceinline__ float fast_ex2(float x) {
    float r; asm("ex2.approx.f32 %0, %1;" : "=f"(r) : "f"(x)); return r;
}
__device__ __forceinline__ float fast_rcp(float x) {
    float r; asm("rcp.approx.f32 %0, %1;" : "=f"(r) : "f"(x)); return r;
}
__device__ __forceinline__ u64 pk2(float lo, float hi) {
    u64 r; asm("mov.b64 %0, {%1, %2};" : "=l"(r) : "f"(lo), "f"(hi)); return r;
}
__device__ __forceinline__ void unpk2(u64 v, float& lo, float& hi) {
    asm("mov.b64 {%0, %1}, %2;" : "=f"(lo), "=f"(hi) : "l"(v));
}
__device__ __forceinline__ u64 fma2(u64 a, u64 b, u64 c) {
    u64 d; asm("fma.rn.f32x2 %0, %1, %2, %3;" : "=l"(d) : "l"(a), "l"(b), "l"(c));
    return d;
}

// unit u = q*16 + g*4 + c  ->  float slot ((g*4+q)*4 + c).
// For fixed g the 4 quad-lanes read 4 consecutive 16B chunks: conflict-free.
#define PK(g, q, c) (((g) * 4 + (q)) * 4 + (c))

// ---------------------------------------------------------------- K1: ODE ---
__global__ __launch_bounds__(128, 8)
void node_ode_kernel(
    const float* __restrict__ y0g,  const float* __restrict__ tg,
    const float* __restrict__ W1,   const float* __restrict__ b1,
    const float* __restrict__ W2,   const float* __restrict__ b2,
    int B)
{
    __shared__ __align__(16) float sWA[H];      // W1 row0 * C, packed
    __shared__ __align__(16) float sWB[H];      // W1 row1 * C, packed
    __shared__ __align__(16) float sBB[H];      // b1  * C, packed
    __shared__ __align__(16) float sVV[H * 2];  // {-2*W2[u][0], -2*W2[u][1]} packed
    __shared__ float sS[2];
    __shared__ float sdt[TT - 1];

    const float C = 2.88539008177792681472f;    // 2*log2(e)
    const int tid = threadIdx.x;

    if (tid < H) {
        int u = tid;
        int q = u >> 4, r = u & 15, g = r >> 2, c = r & 3;
        int p = PK(g, q, c);
        sWA[p] = W1[u] * C;
        sWB[p] = W1[H + u] * C;
        sBB[p] = b1[u] * C;
        sVV[p * 2 + 0] = -2.0f * W2[u * 2 + 0];
        sVV[p * 2 + 1] = -2.0f * W2[u * 2 + 1];
    }
    if (tid >= H && tid < H + 2) {
        int c = tid - H;
        float s = b2[c];
        #pragma unroll 8
        for (int j = 0; j < H; j++) s += W2[j * 2 + c];
        sS[c] = s;
    }
    for (int i = tid; i < TT - 1; i += 128)
        sdt[i] = tg[i + 1] - tg[i];
    __syncthreads();

    const int gid = blockIdx.x * 128 + tid;
    const int eA = gid >> 2;           // first element
    const int q  = gid & 3;            // quad slot
    const int half = B >> 1;
    if (eA >= half) return;
    const int eB = eA + half;          // second element

    float yaA = y0g[eA * 2 + 0], ybA = y0g[eA * 2 + 1];
    float yaB = y0g[eB * 2 + 0], ybB = y0g[eB * 2 + 1];
    const float S0 = sS[0], S1 = sS[1];

    for (int s = 0; s < TT - 1; s++) {
        const float dt = sdt[s];
        const u64 pAa = pk2(yaA, yaA), pAb = pk2(ybA, ybA);
        const u64 pBa = pk2(yaB, yaB), pBb = pk2(ybB, ybB);
        float accA0 = 0.f, accA1 = 0.f, accB0 = 0.f, accB1 = 0.f;

        #pragma unroll
        for (int g = 0; g < 4; g++) {
            const int base = PK(g, q, 0);
            const ulonglong2 WA = *(const ulonglong2*)&sWA[base];
            const ulonglong2 WB = *(const ulonglong2*)&sWB[base];
            const ulonglong2 BB = *(const ulonglong2*)&sBB[base];
            const float4 V01 = *(const float4*)&sVV[base * 2];
            const float4 V23 = *(const float4*)&sVV[base * 2 + 4];

            // element A
            {
                u64 w01 = fma2(pAa, WA.x, fma2(pAb, WB.x, BB.x));
                u64 w23 = fma2(pAa, WA.y, fma2(pAb, WB.y, BB.y));
                float w0, w1, w2, w3;
                unpk2(w01, w0, w1);
                unpk2(w23, w2, w3);
                w0 = fminf(w0, 30.0f); w1 = fminf(w1, 30.0f);
                w2 = fminf(w2, 30.0f); w3 = fminf(w3, 30.0f);
                float E0 = fast_ex2(w0), E1 = fast_ex2(w1);
                float E2 = fast_ex2(w2), E3 = fast_ex2(w3);
                float a0 = E0 + 1.0f, a2 = E2 + 1.0f;
                float p01 = fmaf(a0, E1, a0);       // a0*(E1+1)
                float p23 = fmaf(a2, E3, a2);       // a2*(E3+1)
                float rinv = fast_rcp(p01 * p23);
                float q01 = rinv * p23, q23 = rinv * p01;
                float r1 = q01 * a0, r0 = fmaf(q01, E1, q01);
                float r3 = q23 * a2, r2 = fmaf(q23, E3, q23);
                accA0 = fmaf(r0, V01.x, accA0); accA1 = fmaf(r0, V01.y, accA1);
                accA0 = fmaf(r1, V01.z, accA0); accA1 = fmaf(r1, V01.w, accA1);
                accA0 = fmaf(r2, V23.x, accA0); accA1 = fmaf(r2, V23.y, accA1);
                accA0 = fmaf(r3, V23.z, accA0); accA1 = fmaf(r3, V23.w, accA1);
            }
            // element B
            {
                u64 w01 = fma2(pBa, WA.x, fma2(pBb, WB.x, BB.x));
                u64 w23 = fma2(pBa, WA.y, fma2(pBb, WB.y, BB.y));
                float w0, w1, w2, w3;
                unpk2(w01, w0, w1);
                unpk2(w23, w2, w3);
                w0 = fminf(w0, 30.0f); w1 = fminf(w1, 30.0f);
                w2 = fminf(w2, 30.0f); w3 = fminf(w3, 30.0f);
                float E0 = fast_ex2(w0), E1 = fast_ex2(w1);
                float E2 = fast_ex2(w2), E3 = fast_ex2(w3);
                float a0 = E0 + 1.0f, a2 = E2 + 1.0f;
                float p01 = fmaf(a0, E1, a0);
                float p23 = fmaf(a2, E3, a2);
                float rinv = fast_rcp(p01 * p23);
                float q01 = rinv * p23, q23 = rinv * p01;
                float r1 = q01 * a0, r0 = fmaf(q01, E1, q01);
                float r3 = q23 * a2, r2 = fmaf(q23, E3, q23);
                accB0 = fmaf(r0, V01.x, accB0); accB1 = fmaf(r0, V01.y, accB1);
                accB0 = fmaf(r1, V01.z, accB0); accB1 = fmaf(r1, V01.w, accB1);
                accB0 = fmaf(r2, V23.x, accB0); accB1 = fmaf(r2, V23.y, accB1);
                accB0 = fmaf(r3, V23.z, accB0); accB1 = fmaf(r3, V23.w, accB1);
            }
        }

        accA0 += __shfl_xor_sync(0xffffffffu, accA0, 1);
        accA0 += __shfl_xor_sync(0xffffffffu, accA0, 2);
        accA1 += __shfl_xor_sync(0xffffffffu, accA1, 1);
        accA1 += __shfl_xor_sync(0xffffffffu, accA1, 2);
        accB0 += __shfl_xor_sync(0xffffffffu, accB0, 1);
        accB0 += __shfl_xor_sync(0xffffffffu, accB0, 2);
        accB1 += __shfl_xor_sync(0xffffffffu, accB1, 1);
        accB1 += __shfl_xor_sync(0xffffffffu, accB1, 2);

        yaA = fmaf(dt, S0 + accA0, yaA);   // identical across the quad
        ybA = fmaf(dt, S1 + accA1, ybA);
        yaB = fmaf(dt, S0 + accB0, yaB);
        ybB = fmaf(dt, S1 + accB1, ybB);
    }

    if (q == 0) {
        g_yT[eA * 2 + 0] = yaA;
        g_yT[eA * 2 + 1] = ybA;
        g_yT[eB * 2 + 0] = yaB;
        g_yT[eB * 2 + 1] = ybB;
    }
}

// --------------------------------------------------------- K2: classifier ---
// 1 thread/elem, warp-broadcast shared reads (proven). Block 64 so the grid
// is 1024 CTAs -> balanced wave across 148 SMs.
__global__ __launch_bounds__(64, 8)
void node_cls_kernel(
    const float* __restrict__ Wc1,  const float* __restrict__ bc1,
    const float* __restrict__ Wc2,  const float* __restrict__ bc2,
    const float* __restrict__ Wc3,  const float* __restrict__ bc3,
    float* __restrict__ out, int B)
{
    __shared__ __align__(16) float sWc1A[H], sWc1B[H], sbc1[H];
    __shared__ __align__(16) float sWc2T[H][H];  // [out_j][in_k]
    __shared__ __align__(16) float sbc2[H];
    __shared__ __align__(16) float4 sWc3[H];     // {w0,w1,w2,0}
    __shared__ float sbc3[NCLS];

    const int tid = threadIdx.x;
    if (tid < H) {
        sWc1A[tid] = Wc1[tid];
        sWc1B[tid] = Wc1[H + tid];
        sbc1[tid]  = bc1[tid];
        sbc2[tid]  = bc2[tid];
        sWc3[tid]  = make_float4(Wc3[tid * 3 + 0], Wc3[tid * 3 + 1],
                                 Wc3[tid * 3 + 2], 0.0f);
    }
    if (tid < NCLS) sbc3[tid] = bc3[tid];
    for (int i = tid; i < H * H; i += 64) {
        sWc2T[i & 63][i >> 6] = Wc2[i];
    }
    __syncthreads();

    const int idx = blockIdx.x * 64 + tid;
    if (idx >= B) return;

    const float ya = g_yT[idx * 2 + 0];
    const float yb = g_yT[idx * 2 + 1];

    float h1[H];
    #pragma unroll
    for (int j = 0; j < H; j++)
        h1[j] = fmaxf(fmaf(ya, sWc1A[j], fmaf(yb, sWc1B[j], sbc1[j])), 0.0f);

    float o0 = sbc3[0], o1 = sbc3[1], o2 = sbc3[2];
    for (int j = 0; j < H; j++) {
        float s0 = sbc2[j], s1 = 0.f, s2 = 0.f, s3 = 0.f;
        #pragma unroll
        for (int k = 0; k < H; k += 4) {
            const float4 w = *(const float4*)&sWc2T[j][k];
            s0 = fmaf(h1[k + 0], w.x, s0);
            s1 = fmaf(h1[k + 1], w.y, s1);
            s2 = fmaf(h1[k + 2], w.z, s2);
            s3 = fmaf(h1[k + 3], w.w, s3);
        }
        float s = fmaxf((s0 + s1) + (s2 + s3), 0.0f);
        const float4 wc = sWc3[j];
        o0 = fmaf(s, wc.x, o0);
        o1 = fmaf(s, wc.y, o1);
        o2 = fmaf(s, wc.z, o2);
    }

    out[idx * 3 + 0] = o0;
    out[idx * 3 + 1] = o1;
    out[idx * 3 + 2] = o2;
}

extern "C" void kernel_launch(void* const* d_in, const int* in_sizes, int n_in,
                              void* d_out, int out_size) {
    const float* y0  = (const float*)d_in[0];
    const float* t   = (const float*)d_in[1];
    const float* W1  = (const float*)d_in[2];
    const float* b1  = (const float*)d_in[3];
    const float* W2  = (const float*)d_in[4];
    const float* b2  = (const float*)d_in[5];
    const float* Wc1 = (const float*)d_in[6];
    const float* bc1 = (const float*)d_in[7];
    const float* Wc2 = (const float*)d_in[8];
    const float* bc2 = (const float*)d_in[9];
    const float* Wc3 = (const float*)d_in[10];
    const float* bc3 = (const float*)d_in[11];
    float* out = (float*)d_out;

    const int B = in_sizes[0] / 2;
    const long long thOde = (long long)B * 2;   // 4 lanes/elem, 2 elems/thread
    node_ode_kernel<<<(int)((thOde + 127) / 128), 128>>>(y0, t, W1, b1, W2, b2, B);
    node_cls_kernel<<<(B + 63) / 64, 64>>>(Wc1, bc1, Wc2, bc2, Wc3, bc3, out, B);
}

// round 13
// speedup vs baseline: 2.1533x; 1.0309x over previous
#include <cuda_runtime.h>

// NeuralODEClassifier, two kernels.
// K1 (ODE): quad = 4 lanes/element, 16 hidden units/lane, 2 elements/thread.
//   Weights in shared (conflict-free quad packing). Batched-rcp sigmoid with
//   fma-fold (a1/a3 never materialized). f32x2 packed FMA for BOTH the input
//   MLP and the accumulation: acc is one u64 {acc0,acc1} per element, updated
//   with fma2(pk2(r,r), {v0,v1}_unit, acc) — same sVV layout, no horizontal
//   add. 64-reg budget (occ 8), 1024 CTAs single wave.
// K2 (classifier): 1 thread/elem, block 128, Wc2 transposed in shared
//   (proven 33us configuration).
//
// tanh(z) = 1 - 2/(2^(C*z)+1), C = 2*log2(e); W1/b1 prescaled by C, the
// (1-2r) fold absorbed into W2 (v = -2*W2, S = colsum(W2)+b2).

#define H 64
#define TT 64
#define NCLS 3
#define BMAX 65536

typedef unsigned long long u64;

__device__ float g_yT[BMAX * 2];

__device__ __forceinline__ float fast_ex2(float x) {
    float r; asm("ex2.approx.f32 %0, %1;" : "=f"(r) : "f"(x)); return r;
}
__device__ __forceinline__ float fast_rcp(float x) {
    float r; asm("rcp.approx.f32 %0, %1;" : "=f"(r) : "f"(x)); return r;
}
__device__ __forceinline__ u64 pk2(float lo, float hi) {
    u64 r; asm("mov.b64 %0, {%1, %2};" : "=l"(r) : "f"(lo), "f"(hi)); return r;
}
__device__ __forceinline__ void unpk2(u64 v, float& lo, float& hi) {
    asm("mov.b64 {%0, %1}, %2;" : "=f"(lo), "=f"(hi) : "l"(v));
}
__device__ __forceinline__ u64 fma2(u64 a, u64 b, u64 c) {
    u64 d; asm("fma.rn.f32x2 %0, %1, %2, %3;" : "=l"(d) : "l"(a), "l"(b), "l"(c));
    return d;
}

// unit u = q*16 + g*4 + c  ->  float slot ((g*4+q)*4 + c).
// For fixed g the 4 quad-lanes read 4 consecutive 16B chunks: conflict-free.
#define PK(g, q, c) (((g) * 4 + (q)) * 4 + (c))

// ---------------------------------------------------------------- K1: ODE ---
__global__ __launch_bounds__(128, 8)
void node_ode_kernel(
    const float* __restrict__ y0g,  const float* __restrict__ tg,
    const float* __restrict__ W1,   const float* __restrict__ b1,
    const float* __restrict__ W2,   const float* __restrict__ b2,
    int B)
{
    __shared__ __align__(16) float sWA[H];      // W1 row0 * C, packed
    __shared__ __align__(16) float sWB[H];      // W1 row1 * C, packed
    __shared__ __align__(16) float sBB[H];      // b1  * C, packed
    __shared__ __align__(16) float sVV[H * 2];  // {-2*W2[u][0], -2*W2[u][1]} per unit, packed
    __shared__ float sS[2];
    __shared__ float sdt[TT - 1];

    const float C = 2.88539008177792681472f;    // 2*log2(e)
    const int tid = threadIdx.x;

    if (tid < H) {
        int u = tid;
        int q = u >> 4, r = u & 15, g = r >> 2, c = r & 3;
        int p = PK(g, q, c);
        sWA[p] = W1[u] * C;
        sWB[p] = W1[H + u] * C;
        sBB[p] = b1[u] * C;
        sVV[p * 2 + 0] = -2.0f * W2[u * 2 + 0];
        sVV[p * 2 + 1] = -2.0f * W2[u * 2 + 1];
    }
    if (tid >= H && tid < H + 2) {
        int c = tid - H;
        float s = b2[c];
        #pragma unroll 8
        for (int j = 0; j < H; j++) s += W2[j * 2 + c];
        sS[c] = s;
    }
    for (int i = tid; i < TT - 1; i += 128)
        sdt[i] = tg[i + 1] - tg[i];
    __syncthreads();

    const int gid = blockIdx.x * 128 + tid;
    const int eA = gid >> 2;           // first element
    const int q  = gid & 3;            // quad slot
    const int half = B >> 1;
    if (eA >= half) return;
    const int eB = eA + half;          // second element

    float yaA = y0g[eA * 2 + 0], ybA = y0g[eA * 2 + 1];
    float yaB = y0g[eB * 2 + 0], ybB = y0g[eB * 2 + 1];
    const float S0 = sS[0], S1 = sS[1];

    for (int s = 0; s < TT - 1; s++) {
        const float dt = sdt[s];
        const u64 pAa = pk2(yaA, yaA), pAb = pk2(ybA, ybA);
        const u64 pBa = pk2(yaB, yaB), pBb = pk2(ybB, ybB);
        u64 accA = 0, accB = 0;        // each = {acc0, acc1}

        #pragma unroll
        for (int g = 0; g < 4; g++) {
            const int base = PK(g, q, 0);
            const ulonglong2 WA = *(const ulonglong2*)&sWA[base];
            const ulonglong2 WB = *(const ulonglong2*)&sWB[base];
            const ulonglong2 BB = *(const ulonglong2*)&sBB[base];
            const ulonglong2 Vp01 = *(const ulonglong2*)&sVV[base * 2];     // unit0, unit1 {v0,v1}
            const ulonglong2 Vp23 = *(const ulonglong2*)&sVV[base * 2 + 4]; // unit2, unit3 {v0,v1}

            // element A
            {
                u64 w01 = fma2(pAa, WA.x, fma2(pAb, WB.x, BB.x));
                u64 w23 = fma2(pAa, WA.y, fma2(pAb, WB.y, BB.y));
                float w0, w1, w2, w3;
                unpk2(w01, w0, w1);
                unpk2(w23, w2, w3);
                w0 = fminf(w0, 30.0f); w1 = fminf(w1, 30.0f);
                w2 = fminf(w2, 30.0f); w3 = fminf(w3, 30.0f);
                float E0 = fast_ex2(w0), E1 = fast_ex2(w1);
                float E2 = fast_ex2(w2), E3 = fast_ex2(w3);
                float a0 = E0 + 1.0f, a2 = E2 + 1.0f;
                float p01 = fmaf(a0, E1, a0);       // a0*(E1+1)
                float p23 = fmaf(a2, E3, a2);       // a2*(E3+1)
                float rinv = fast_rcp(p01 * p23);
                float q01 = rinv * p23, q23 = rinv * p01;
                float r1 = q01 * a0, r0 = fmaf(q01, E1, q01);
                float r3 = q23 * a2, r2 = fmaf(q23, E3, q23);
                accA = fma2(pk2(r0, r0), Vp01.x, accA);
                accA = fma2(pk2(r1, r1), Vp01.y, accA);
                accA = fma2(pk2(r2, r2), Vp23.x, accA);
                accA = fma2(pk2(r3, r3), Vp23.y, accA);
            }
            // element B
            {
                u64 w01 = fma2(pBa, WA.x, fma2(pBb, WB.x, BB.x));
                u64 w23 = fma2(pBa, WA.y, fma2(pBb, WB.y, BB.y));
                float w0, w1, w2, w3;
                unpk2(w01, w0, w1);
                unpk2(w23, w2, w3);
                w0 = fminf(w0, 30.0f); w1 = fminf(w1, 30.0f);
                w2 = fminf(w2, 30.0f); w3 = fminf(w3, 30.0f);
                float E0 = fast_ex2(w0), E1 = fast_ex2(w1);
                float E2 = fast_ex2(w2), E3 = fast_ex2(w3);
                float a0 = E0 + 1.0f, a2 = E2 + 1.0f;
                float p01 = fmaf(a0, E1, a0);
                float p23 = fmaf(a2, E3, a2);
                float rinv = fast_rcp(p01 * p23);
                float q01 = rinv * p23, q23 = rinv * p01;
                float r1 = q01 * a0, r0 = fmaf(q01, E1, q01);
                float r3 = q23 * a2, r2 = fmaf(q23, E3, q23);
                accB = fma2(pk2(r0, r0), Vp01.x, accB);
                accB = fma2(pk2(r1, r1), Vp01.y, accB);
                accB = fma2(pk2(r2, r2), Vp23.x, accB);
                accB = fma2(pk2(r3, r3), Vp23.y, accB);
            }
        }

        float accA0, accA1, accB0, accB1;
        unpk2(accA, accA0, accA1);
        unpk2(accB, accB0, accB1);
        accA0 += __shfl_xor_sync(0xffffffffu, accA0, 1);
        accA0 += __shfl_xor_sync(0xffffffffu, accA0, 2);
        accA1 += __shfl_xor_sync(0xffffffffu, accA1, 1);
        accA1 += __shfl_xor_sync(0xffffffffu, accA1, 2);
        accB0 += __shfl_xor_sync(0xffffffffu, accB0, 1);
        accB0 += __shfl_xor_sync(0xffffffffu, accB0, 2);
        accB1 += __shfl_xor_sync(0xffffffffu, accB1, 1);
        accB1 += __shfl_xor_sync(0xffffffffu, accB1, 2);

        yaA = fmaf(dt, S0 + accA0, yaA);   // identical across the quad
        ybA = fmaf(dt, S1 + accA1, ybA);
        yaB = fmaf(dt, S0 + accB0, yaB);
        ybB = fmaf(dt, S1 + accB1, ybB);
    }

    if (q == 0) {
        g_yT[eA * 2 + 0] = yaA;
        g_yT[eA * 2 + 1] = ybA;
        g_yT[eB * 2 + 0] = yaB;
        g_yT[eB * 2 + 1] = ybB;
    }
}

// --------------------------------------------------------- K2: classifier ---
// 1 thread/elem, block 128, warp-broadcast shared reads (proven 33us).
__global__ __launch_bounds__(128, 4)
void node_cls_kernel(
    const float* __restrict__ Wc1,  const float* __restrict__ bc1,
    const float* __restrict__ Wc2,  const float* __restrict__ bc2,
    const float* __restrict__ Wc3,  const float* __restrict__ bc3,
    float* __restrict__ out, int B)
{
    __shared__ __align__(16) float sWc1A[H], sWc1B[H], sbc1[H];
    __shared__ __align__(16) float sWc2T[H][H];  // [out_j][in_k]
    __shared__ __align__(16) float sbc2[H];
    __shared__ __align__(16) float4 sWc3[H];     // {w0,w1,w2,0}
    __shared__ float sbc3[NCLS];

    const int tid = threadIdx.x;
    if (tid < H) {
        sWc1A[tid] = Wc1[tid];
        sWc1B[tid] = Wc1[H + tid];
        sbc1[tid]  = bc1[tid];
        sbc2[tid]  = bc2[tid];
        sWc3[tid]  = make_float4(Wc3[tid * 3 + 0], Wc3[tid * 3 + 1],
                                 Wc3[tid * 3 + 2], 0.0f);
    }
    if (tid < NCLS) sbc3[tid] = bc3[tid];
    for (int i = tid; i < H * H; i += 128) {
        sWc2T[i & 63][i >> 6] = Wc2[i];
    }
    __syncthreads();

    const int idx = blockIdx.x * 128 + tid;
    if (idx >= B) return;

    const float ya = g_yT[idx * 2 + 0];
    const float yb = g_yT[idx * 2 + 1];

    float h1[H];
    #pragma unroll
    for (int j = 0; j < H; j++)
        h1[j] = fmaxf(fmaf(ya, sWc1A[j], fmaf(yb, sWc1B[j], sbc1[j])), 0.0f);

    float o0 = sbc3[0], o1 = sbc3[1], o2 = sbc3[2];
    for (int j = 0; j < H; j++) {
        float s0 = sbc2[j], s1 = 0.f, s2 = 0.f, s3 = 0.f;
        #pragma unroll
        for (int k = 0; k < H; k += 4) {
            const float4 w = *(const float4*)&sWc2T[j][k];
            s0 = fmaf(h1[k + 0], w.x, s0);
            s1 = fmaf(h1[k + 1], w.y, s1);
            s2 = fmaf(h1[k + 2], w.z, s2);
            s3 = fmaf(h1[k + 3], w.w, s3);
        }
        float s = fmaxf((s0 + s1) + (s2 + s3), 0.0f);
        const float4 wc = sWc3[j];
        o0 = fmaf(s, wc.x, o0);
        o1 = fmaf(s, wc.y, o1);
        o2 = fmaf(s, wc.z, o2);
    }

    out[idx * 3 + 0] = o0;
    out[idx * 3 + 1] = o1;
    out[idx * 3 + 2] = o2;
}

extern "C" void kernel_launch(void* const* d_in, const int* in_sizes, int n_in,
                              void* d_out, int out_size) {
    const float* y0  = (const float*)d_in[0];
    const float* t   = (const float*)d_in[1];
    const float* W1  = (const float*)d_in[2];
    const float* b1  = (const float*)d_in[3];
    const float* W2  = (const float*)d_in[4];
    const float* b2  = (const float*)d_in[5];
    const float* Wc1 = (const float*)d_in[6];
    const float* bc1 = (const float*)d_in[7];
    const float* Wc2 = (const float*)d_in[8];
    const float* bc2 = (const float*)d_in[9];
    const float* Wc3 = (const float*)d_in[10];
    const float* bc3 = (const float*)d_in[11];
    float* out = (float*)d_out;

    const int B = in_sizes[0] / 2;
    const long long thOde = (long long)B * 2;   // 4 lanes/elem, 2 elems/thread
    node_ode_kernel<<<(int)((thOde + 127) / 128), 128>>>(y0, t, W1, b1, W2, b2, B);
    node_cls_kernel<<<(B + 127) / 128, 128>>>(Wc1, bc1, Wc2, bc2, Wc3, bc3, out, B);
}